// round 9
// baseline (speedup 1.0000x reference)
#include <cuda_runtime.h>

#define NOBJ   4096
#define DIM    1024
#define DIM2   2048
#define NREL   8
#define NPAIR  65536

// Scratch (device globals — no allocation allowed)
__device__ float g_Mpart[16 * NREL * DIM2]; // split-K partials, 1 MB
__device__ float g_M[NREL * DIM2];          // fused weight M = W2 @ W1, 64 KB
__device__ float g_c[NREL];                 // fused bias c = W2@b1 + b2
__device__ float g_U[NOBJ * 16];            // per-object projections, 256 KB
                                            //   [o][0:8]  = f·M[:, :1024]ᵀ
                                            //   [o][8:16] = f·M[:, 1024:]ᵀ + c

// Packed fp32x2 FMA: d = a*b + d elementwise on (lo,hi) pairs.
__device__ __forceinline__ void ffma2(unsigned long long& acc,
                                      unsigned long long a,
                                      unsigned long long b) {
    asm("fma.rn.f32x2 %0, %1, %2, %0;" : "+l"(acc) : "l"(a), "l"(b));
}

__device__ __forceinline__ float4 f4fma(float s, float4 v, float4 a) {
    a.x += s * v.x; a.y += s * v.y; a.z += s * v.z; a.w += s * v.w;
    return a;
}

// ---------------------------------------------------------------------------
// Stage A: Mpart[ic][r][j] = sum_{i in ichunk} W2[r][i] * W1[i][j]
// Grid 256 = (16 j-chunks x 16 i-chunks), 256 threads.
// ---------------------------------------------------------------------------
__global__ void __launch_bounds__(256) m_partial_kernel(const float* __restrict__ W1,
                                                        const float* __restrict__ W2) {
    __shared__ float  sW2[NREL][64];     // 2 KB
    __shared__ float4 sAcc[8][256];      // 32 KB [iw][r*32+jq]
    const int tx = threadIdx.x;
    const int jc = blockIdx.x & 15;
    const int ic = blockIdx.x >> 4;
    const int jbase = jc * 128;
    const int ibase = ic * 64;

    if (tx < 128) {     // stage W2 chunk: 8 r x 64 i
        const int r = tx >> 4, q = tx & 15;
        *(float4*)&sW2[r][q * 4] = __ldg((const float4*)&W2[r * DIM + ibase + q * 4]);
    }
    __syncthreads();

    const int jq = tx & 31;          // float4 column within j-chunk
    const int iw = tx >> 5;          // warp id -> 8 i's

    float4 w1v[8];
#pragma unroll
    for (int u = 0; u < 8; u++) {    // all 8 loads independent
        const int i = ibase + iw * 8 + u;
        w1v[u] = __ldg((const float4*)(W1 + i * DIM2 + jbase + jq * 4));
    }

    float4 acc[NREL];
#pragma unroll
    for (int r = 0; r < NREL; r++) acc[r] = make_float4(0.f, 0.f, 0.f, 0.f);
#pragma unroll
    for (int u = 0; u < 8; u++) {
        const int il = iw * 8 + u;
#pragma unroll
        for (int r = 0; r < NREL; r++) acc[r] = f4fma(sW2[r][il], w1v[u], acc[r]);
    }
#pragma unroll
    for (int r = 0; r < NREL; r++) sAcc[iw][r * 32 + jq] = acc[r];
    __syncthreads();

    const int r = tx >> 5, jq2 = tx & 31;
    float4 s = sAcc[0][r * 32 + jq2];
#pragma unroll
    for (int w = 1; w < 8; w++) {
        float4 p = sAcc[w][r * 32 + jq2];
        s.x += p.x; s.y += p.y; s.z += p.z; s.w += p.w;
    }
    ((float4*)g_Mpart)[ic * 4096 + r * 512 + jc * 32 + jq2] = s;
}

// ---------------------------------------------------------------------------
// Stage B: M = sum over 16 i-chunks (fixed order), float4, MLP=16.
// Block 0 additionally computes c[r] = W2[r]·b1 + b2[r]. Grid 16 x 256.
// ---------------------------------------------------------------------------
__global__ void __launch_bounds__(256) m_reduce_kernel(const float* __restrict__ W2,
                                                       const float* __restrict__ b1,
                                                       const float* __restrict__ b2) {
    const int g4 = blockIdx.x * 256 + threadIdx.x;    // 0..4095
    const float4* __restrict__ P4 = (const float4*)g_Mpart;
    float4 s = P4[g4];
#pragma unroll
    for (int ic = 1; ic < 16; ic++) {
        float4 p = P4[ic * 4096 + g4];
        s.x += p.x; s.y += p.y; s.z += p.z; s.w += p.w;
    }
    ((float4*)g_M)[g4] = s;

    if (blockIdx.x == 0) {
        const int w = threadIdx.x >> 5, lane = threadIdx.x & 31;
        float t = 0.f;
        for (int i = lane; i < DIM; i += 32) t += b1[i] * W2[w * DIM + i];
#pragma unroll
        for (int off = 16; off; off >>= 1)
            t += __shfl_xor_sync(0xffffffffu, t, off);
        if (lane == 0) g_c[w] = t + b2[w];
    }
}

// ---------------------------------------------------------------------------
// U table: U[o][j] = feats[o] · Mrow_j   (+ c[j] folded into the object half)
// Warp task: 2 objects x 8 j-columns  -> 4096 tasks over 4096 warps.
// Grid 512 x 256 (28 warps/SM resident). ~70 regs/thread.
// ---------------------------------------------------------------------------
__global__ void __launch_bounds__(256) u_kernel(const float* __restrict__ feats) {
    const int gw   = (blockIdx.x * 256 + threadIdx.x) >> 5;  // 0..4095
    const int lane = threadIdx.x & 31;
    const int duo  = gw >> 1;          // 0..2047 -> objects 2*duo, 2*duo+1
    const int half = gw & 1;           // 0: sub cols, 1: obj cols
    const int obase = duo * 2;

    const longlong2* __restrict__ F2 = (const longlong2*)feats;  // 256 per row
    const longlong2* __restrict__ M2 = (const longlong2*)g_M;    // row j at j*512
    const int jbase = half * 256;      // +1024 floats for obj half

    unsigned long long acc[2][8];
#pragma unroll
    for (int k = 0; k < 2; k++)
#pragma unroll
        for (int j = 0; j < 8; j++) acc[k][j] = 0ull;

#pragma unroll 1
    for (int t = 0; t < 8; t++) {      // 8 x 32 lanes x 4 floats = 1024 d
        const int idx = t * 32 + lane;
        unsigned long long fa[2], fb[2];
#pragma unroll
        for (int k = 0; k < 2; k++) {
            longlong2 fv = __ldg(F2 + (obase + k) * 256 + idx);
            fa[k] = (unsigned long long)fv.x;
            fb[k] = (unsigned long long)fv.y;
        }
#pragma unroll
        for (int j = 0; j < 8; j++) {
            longlong2 mv = __ldg(M2 + j * 512 + jbase + idx);
            const unsigned long long ma = (unsigned long long)mv.x;
            const unsigned long long mb = (unsigned long long)mv.y;
#pragma unroll
            for (int k = 0; k < 2; k++) {
                ffma2(acc[k][j], fa[k], ma);
                ffma2(acc[k][j], fb[k], mb);
            }
        }
    }

    // Collapse packed halves -> 16 scalar partials per lane (vi = k*8+j).
    float v[16];
#pragma unroll
    for (int k = 0; k < 2; k++)
#pragma unroll
        for (int j = 0; j < 8; j++) {
            float2 p = *(float2*)&acc[k][j];
            v[k * 8 + j] = p.x + p.y;
        }

    // Butterfly fold over 16 values: stages d=1,2,4,8 (15 shfl), then a
    // final full-sum exchange at d=16. Lanes L and L+16 end with the same
    // output index vi = bitrev4(L & 15); lanes 0..15 store.
    int nv = 16;
#pragma unroll
    for (int d = 1; d < 16; d <<= 1) {
        nv >>= 1;
        const bool up = (lane & d) != 0;
#pragma unroll
        for (int i = 0; i < 8; i++) {
            if (i < nv) {
                float send = up ? v[i] : v[i + nv];
                float recv = __shfl_xor_sync(0xffffffffu, send, d);
                v[i] = (up ? v[i + nv] : v[i]) + recv;
            }
        }
    }
    v[0] += __shfl_xor_sync(0xffffffffu, v[0], 16);

    if (lane < 16) {
        const int vi = __brev(lane & 15) >> 28;   // bitrev4
        const int k = vi >> 3;                    // object within duo
        const int j = vi & 7;                     // output column
        const float bias = half ? g_c[j] : 0.f;   // fold c into object half
        g_U[(obase + k) * 16 + half * 8 + j] = v[0] + bias;
    }
}

// ---------------------------------------------------------------------------
// out[p][r] = U[s_p][r] + U[o_p][8+r]   (c already folded into U's obj half)
// 1 pair per thread, 512 blocks x 128 threads = 65536 threads (2048 warps).
// ---------------------------------------------------------------------------
__global__ void __launch_bounds__(128) gather_kernel(const int* __restrict__ pairs,
                                                     float* __restrict__ out) {
    const int p = blockIdx.x * 128 + threadIdx.x;    // 0..65535
    int2 pr = __ldg(&((const int2*)pairs)[p]);
    const float4* __restrict__ U4 = (const float4*)g_U;
    float4 a0 = __ldg(&U4[pr.x * 4 + 0]);
    float4 a1 = __ldg(&U4[pr.x * 4 + 1]);
    float4 b0 = __ldg(&U4[pr.y * 4 + 2]);
    float4 b1 = __ldg(&U4[pr.y * 4 + 3]);
    float4 r0, r1;
    r0.x = a0.x + b0.x;  r0.y = a0.y + b0.y;
    r0.z = a0.z + b0.z;  r0.w = a0.w + b0.w;
    r1.x = a1.x + b1.x;  r1.y = a1.y + b1.y;
    r1.z = a1.z + b1.z;  r1.w = a1.w + b1.w;
    float4* __restrict__ O4 = (float4*)out;
    O4[p * 2 + 0] = r0;
    O4[p * 2 + 1] = r1;
}

extern "C" void kernel_launch(void* const* d_in, const int* in_sizes, int n_in,
                              void* d_out, int out_size) {
    const float* feats = (const float*)d_in[0];   // (4096, 1024) f32
    const int*   pairs = (const int*)d_in[1];     // (65536, 2) i32
    const float* W1    = (const float*)d_in[2];   // (1024, 2048) f32
    const float* b1    = (const float*)d_in[3];   // (1024,) f32
    const float* W2    = (const float*)d_in[4];   // (8, 1024) f32
    const float* b2    = (const float*)d_in[5];   // (8,) f32
    float*       out   = (float*)d_out;           // (65536, 8) f32

    m_partial_kernel<<<256, 256>>>(W1, W2);
    m_reduce_kernel<<<16, 256>>>(W2, b1, b2);
    u_kernel<<<512, 256>>>(feats);
    gather_kernel<<<512, 128>>>(pairs, out);
}

// round 11
// speedup vs baseline: 1.0667x; 1.0667x over previous
#include <cuda_runtime.h>

#define NOBJ   4096
#define DIM    1024
#define DIM2   2048
#define NREL   8
#define NPAIR  65536

// Scratch (device globals — no allocation allowed)
__device__ float g_M[NREL * DIM2];   // fused weight M = W2 @ W1, 64 KB
__device__ float g_c[NREL];          // fused bias c = W2@b1 + b2
__device__ float g_U[NOBJ * 16];     // per-object projections, 256 KB
                                     //   [o][0:8]  = feats[o]·M[:, :1024]ᵀ
                                     //   [o][8:16] = feats[o]·M[:, 1024:]ᵀ + c

// Packed fp32x2 FMA: d = a*b + d elementwise on (lo,hi) pairs.
__device__ __forceinline__ void ffma2(unsigned long long& acc,
                                      unsigned long long a,
                                      unsigned long long b) {
    asm("fma.rn.f32x2 %0, %1, %2, %0;" : "+l"(acc) : "l"(a), "l"(b));
}

// ---------------------------------------------------------------------------
// M[r][j] = sum_i W2[r][i] * W1[i][j]  (+ block 0 computes c = W2·b1 + b2)
// Grid 128 x 256. Block b owns 16 j-columns; thread (jloc = t&15, ic = t>>4)
// accumulates 64 i's with 8-deep load batching (MLP=8), then an in-block
// fixed-order smem reduction over the 16 i-chunks. W1 read exactly once.
// ---------------------------------------------------------------------------
__global__ void __launch_bounds__(256) m_kernel(const float* __restrict__ W1,
                                                const float* __restrict__ W2,
                                                const float* __restrict__ b1,
                                                const float* __restrict__ b2) {
    __shared__ float sW2[NREL][DIM];       // 32 KB
    __shared__ float sAcc[16][NREL][16];   // 8 KB  [ichunk][r][jloc]
    const int tx = threadIdx.x;

    const float4* __restrict__ W24 = (const float4*)W2;
    float4* sW24 = (float4*)&sW2[0][0];
    for (int i = tx; i < (NREL * DIM) / 4; i += 256) sW24[i] = W24[i];
    __syncthreads();

    const int jloc  = tx & 15;
    const int ic    = tx >> 4;                 // 0..15
    const int j     = blockIdx.x * 16 + jloc;
    const int ibase = ic * 64;

    float acc[NREL];
#pragma unroll
    for (int r = 0; r < NREL; r++) acc[r] = 0.f;

#pragma unroll 1
    for (int ib = 0; ib < 8; ib++) {           // 8 batches of 8 i's
        float w1v[8];
#pragma unroll
        for (int u = 0; u < 8; u++)            // 8 independent loads (MLP=8)
            w1v[u] = __ldg(&W1[(ibase + ib * 8 + u) * DIM2 + j]);
#pragma unroll
        for (int u = 0; u < 8; u++) {
            const int i = ibase + ib * 8 + u;
#pragma unroll
            for (int r = 0; r < NREL; r++) acc[r] += sW2[r][i] * w1v[u];
        }
    }
#pragma unroll
    for (int r = 0; r < NREL; r++) sAcc[ic][r][jloc] = acc[r];
    __syncthreads();

    if (tx < 128) {
        const int r = tx >> 4, jl = tx & 15;
        float s = 0.f;
#pragma unroll
        for (int c = 0; c < 16; c++) s += sAcc[c][r][jl];   // fixed order
        g_M[r * DIM2 + blockIdx.x * 16 + jl] = s;
    }

    if (blockIdx.x == 0) {                 // c[r] = W2[r]·b1 + b2[r]
        const int w = tx >> 5, lane = tx & 31;
        float t = 0.f;
        for (int i = lane; i < DIM; i += 32) t += b1[i] * sW2[w][i];
#pragma unroll
        for (int off = 16; off; off >>= 1)
            t += __shfl_xor_sync(0xffffffffu, t, off);
        if (lane == 0) g_c[w] = t + b2[w];
    }
}

// ---------------------------------------------------------------------------
// U table: U[o][j] = feats[o] · Mrow_j   (+ c[j] folded into the object half)
// Warp w -> pair = w>>1 (4 objects), half = w&1 (8 j-columns).
// Packed f32x2 FMAs, butterfly-fold reduction. Grid 256 x 256 (2048 warps).
// ---------------------------------------------------------------------------
__global__ void __launch_bounds__(256) u_kernel(const float* __restrict__ feats) {
    const int gw   = (blockIdx.x * 256 + threadIdx.x) >> 5;  // 0..2047
    const int lane = threadIdx.x & 31;
    const int pair = gw >> 1;
    const int half = gw & 1;           // 0: sub cols, 1: obj cols
    const int obase = pair * 4;

    const longlong2* __restrict__ F2 = (const longlong2*)feats;  // 256 per row
    const longlong2* __restrict__ M2 = (const longlong2*)g_M;    // row j at j*512
    const int jbase = half * 256;      // +1024 floats for obj half

    unsigned long long acc[4][8];
#pragma unroll
    for (int k = 0; k < 4; k++)
#pragma unroll
        for (int j = 0; j < 8; j++) acc[k][j] = 0ull;

#pragma unroll 1
    for (int t = 0; t < 8; t++) {      // 8 x 32 lanes x 4 floats = 1024 d
        const int idx = t * 32 + lane;
        unsigned long long fa[4], fb[4];
#pragma unroll
        for (int k = 0; k < 4; k++) {
            longlong2 fv = __ldg(F2 + (obase + k) * 256 + idx);
            fa[k] = (unsigned long long)fv.x;
            fb[k] = (unsigned long long)fv.y;
        }
#pragma unroll
        for (int j = 0; j < 8; j++) {
            longlong2 mv = __ldg(M2 + j * 512 + jbase + idx);
            const unsigned long long ma = (unsigned long long)mv.x;
            const unsigned long long mb = (unsigned long long)mv.y;
#pragma unroll
            for (int k = 0; k < 4; k++) {
                ffma2(acc[k][j], fa[k], ma);
                ffma2(acc[k][j], fb[k], mb);
            }
        }
    }

    // Collapse packed halves -> 32 scalar partials per lane (vi = k*8+j).
    float v[32];
#pragma unroll
    for (int k = 0; k < 4; k++)
#pragma unroll
        for (int j = 0; j < 8; j++) {
            float2 p = *(float2*)&acc[k][j];
            v[k * 8 + j] = p.x + p.y;
        }

    // Butterfly fold: 5 stages, 31 shfl. Lane L ends with the full sum of
    // original index bitrev5(L) in v[0].
    int nv = 32;
#pragma unroll
    for (int d = 1; d < 32; d <<= 1) {
        nv >>= 1;
        const bool up = (lane & d) != 0;
#pragma unroll
        for (int i = 0; i < 16; i++) {
            if (i < nv) {
                float send = up ? v[i] : v[i + nv];
                float recv = __shfl_xor_sync(0xffffffffu, send, d);
                v[i] = (up ? v[i + nv] : v[i]) + recv;
            }
        }
    }

    const int vi = __brev(lane) >> 27;   // bitrev5
    const int k = vi >> 3;
    const int j = vi & 7;
    const float bias = half ? g_c[j] : 0.f;   // fold c into object half
    g_U[(obase + k) * 16 + half * 8 + j] = v[0] + bias;
}

// ---------------------------------------------------------------------------
// out[p][r] = U[s_p][r] + U[o_p][8+r]   (c already folded into U's obj half)
// 1 pair per thread, grid 256 x 256 = 65536 threads.
// ---------------------------------------------------------------------------
__global__ void __launch_bounds__(256) gather_kernel(const int* __restrict__ pairs,
                                                     float* __restrict__ out) {
    const int p = blockIdx.x * 256 + threadIdx.x;    // 0..65535
    int2 pr = __ldg(&((const int2*)pairs)[p]);
    const float4* __restrict__ U4 = (const float4*)g_U;
    float4 a0 = __ldg(&U4[pr.x * 4 + 0]);
    float4 a1 = __ldg(&U4[pr.x * 4 + 1]);
    float4 b0 = __ldg(&U4[pr.y * 4 + 2]);
    float4 b1 = __ldg(&U4[pr.y * 4 + 3]);
    float4 r0, r1;
    r0.x = a0.x + b0.x;  r0.y = a0.y + b0.y;
    r0.z = a0.z + b0.z;  r0.w = a0.w + b0.w;
    r1.x = a1.x + b1.x;  r1.y = a1.y + b1.y;
    r1.z = a1.z + b1.z;  r1.w = a1.w + b1.w;
    float4* __restrict__ O4 = (float4*)out;
    O4[p * 2 + 0] = r0;
    O4[p * 2 + 1] = r1;
}

extern "C" void kernel_launch(void* const* d_in, const int* in_sizes, int n_in,
                              void* d_out, int out_size) {
    const float* feats = (const float*)d_in[0];   // (4096, 1024) f32
    const int*   pairs = (const int*)d_in[1];     // (65536, 2) i32
    const float* W1    = (const float*)d_in[2];   // (1024, 2048) f32
    const float* b1    = (const float*)d_in[3];   // (1024,) f32
    const float* W2    = (const float*)d_in[4];   // (8, 1024) f32
    const float* b2    = (const float*)d_in[5];   // (8,) f32
    float*       out   = (float*)d_out;           // (65536, 8) f32

    m_kernel<<<128, 256>>>(W1, W2, b1, b2);
    u_kernel<<<256, 256>>>(feats);
    gather_kernel<<<256, 256>>>(pairs, out);
}

// round 12
// speedup vs baseline: 1.7306x; 1.6224x over previous
#include <cuda_runtime.h>

#define NOBJ   4096
#define DIM    1024
#define DIM2   2048
#define NREL   8
#define NPAIR  65536

// Scratch (device globals — no allocation allowed)
__device__ float g_M[NREL * DIM2];   // fused weight M = W2 @ W1, 64 KB
__device__ float g_c[NREL];          // fused bias c = W2@b1 + b2
__device__ float g_U[NOBJ * 16];     // per-object projections, 256 KB
                                     //   [o][0:8]  = feats[o]·M[:, :1024]ᵀ
                                     //   [o][8:16] = feats[o]·M[:, 1024:]ᵀ + c

// Packed fp32x2 FMA: d = a*b + d elementwise on (lo,hi) pairs.
__device__ __forceinline__ void ffma2(unsigned long long& acc,
                                      unsigned long long a,
                                      unsigned long long b) {
    asm("fma.rn.f32x2 %0, %1, %2, %0;" : "+l"(acc) : "l"(a), "l"(b));
}

// ---------------------------------------------------------------------------
// M[r][j] = sum_i W2[r][i] * W1[i][j]  (+ block 0 computes c = W2·b1 + b2)
// Grid 128 x 256 — exact R4 body (best measured anchor).
// ---------------------------------------------------------------------------
__global__ void __launch_bounds__(256) m_kernel(const float* __restrict__ W1,
                                                const float* __restrict__ W2,
                                                const float* __restrict__ b1,
                                                const float* __restrict__ b2) {
    __shared__ float sW2[NREL][DIM];       // 32 KB
    __shared__ float sAcc[16][NREL][16];   // 8 KB  [ichunk][r][jloc]
    const int tx = threadIdx.x;

    const float4* __restrict__ W24 = (const float4*)W2;
    float4* sW24 = (float4*)&sW2[0][0];
    for (int i = tx; i < (NREL * DIM) / 4; i += 256) sW24[i] = W24[i];
    __syncthreads();

    const int jloc  = tx & 15;
    const int ic    = tx >> 4;                 // 0..15
    const int j     = blockIdx.x * 16 + jloc;
    const int ibase = ic * 64;

    float acc[NREL];
#pragma unroll
    for (int r = 0; r < NREL; r++) acc[r] = 0.f;

#pragma unroll 8
    for (int ii = 0; ii < 64; ii++) {
        const int i = ibase + ii;
        float w1 = __ldg(&W1[i * DIM2 + j]);
#pragma unroll
        for (int r = 0; r < NREL; r++) acc[r] += sW2[r][i] * w1;
    }
#pragma unroll
    for (int r = 0; r < NREL; r++) sAcc[ic][r][jloc] = acc[r];
    __syncthreads();

    if (tx < 128) {
        const int r = tx >> 4, jl = tx & 15;
        float s = 0.f;
#pragma unroll
        for (int c = 0; c < 16; c++) s += sAcc[c][r][jl];   // fixed order
        g_M[r * DIM2 + blockIdx.x * 16 + jl] = s;
    }

    if (blockIdx.x == 0) {                 // c[r] = W2[r]·b1 + b2[r]
        const int w = tx >> 5, lane = tx & 31;
        float t = 0.f;
        for (int i = lane; i < DIM; i += 32) t += b1[i] * sW2[w][i];
#pragma unroll
        for (int off = 16; off; off >>= 1)
            t += __shfl_xor_sync(0xffffffffu, t, off);
        if (lane == 0) g_c[w] = t + b2[w];
    }
}

// ---------------------------------------------------------------------------
// U table: U[o][j] = feats[o] · Mrow_j   (+ c[j] folded into the object half)
// Exact R4 body + PDL: launches during m_kernel's drain; waits for m before
// touching g_M / g_c. Grid 256 x 256 (2048 warps).
// ---------------------------------------------------------------------------
__global__ void __launch_bounds__(256) u_kernel(const float* __restrict__ feats) {
    const int gw   = (blockIdx.x * 256 + threadIdx.x) >> 5;  // 0..2047
    const int lane = threadIdx.x & 31;
    const int pair = gw >> 1;
    const int half = gw & 1;           // 0: sub cols, 1: obj cols
    const int obase = pair * 4;

    const longlong2* __restrict__ F2 = (const longlong2*)feats;  // 256 per row
    const longlong2* __restrict__ M2 = (const longlong2*)g_M;    // row j at j*512
    const int jbase = half * 256;      // +1024 floats for obj half

    // Prologue done (index math only) — now wait for m_kernel's writes.
    cudaGridDependencySynchronize();

    unsigned long long acc[4][8];
#pragma unroll
    for (int k = 0; k < 4; k++)
#pragma unroll
        for (int j = 0; j < 8; j++) acc[k][j] = 0ull;

#pragma unroll 1
    for (int t = 0; t < 8; t++) {      // 8 x 32 lanes x 4 floats = 1024 d
        const int idx = t * 32 + lane;
        unsigned long long fa[4], fb[4];
#pragma unroll
        for (int k = 0; k < 4; k++) {
            longlong2 fv = __ldg(F2 + (obase + k) * 256 + idx);
            fa[k] = (unsigned long long)fv.x;
            fb[k] = (unsigned long long)fv.y;
        }
#pragma unroll
        for (int j = 0; j < 8; j++) {
            longlong2 mv = __ldg(M2 + j * 512 + jbase + idx);
            const unsigned long long ma = (unsigned long long)mv.x;
            const unsigned long long mb = (unsigned long long)mv.y;
#pragma unroll
            for (int k = 0; k < 4; k++) {
                ffma2(acc[k][j], fa[k], ma);
                ffma2(acc[k][j], fb[k], mb);
            }
        }
    }

    // Collapse packed halves -> 32 scalar partials per lane (vi = k*8+j).
    float v[32];
#pragma unroll
    for (int k = 0; k < 4; k++)
#pragma unroll
        for (int j = 0; j < 8; j++) {
            float2 p = *(float2*)&acc[k][j];
            v[k * 8 + j] = p.x + p.y;
        }

    // Butterfly fold: 5 stages, 31 shfl. Lane L ends with the full sum of
    // original index bitrev5(L) in v[0].
    int nv = 32;
#pragma unroll
    for (int d = 1; d < 32; d <<= 1) {
        nv >>= 1;
        const bool up = (lane & d) != 0;
#pragma unroll
        for (int i = 0; i < 16; i++) {
            if (i < nv) {
                float send = up ? v[i] : v[i + nv];
                float recv = __shfl_xor_sync(0xffffffffu, send, d);
                v[i] = (up ? v[i + nv] : v[i]) + recv;
            }
        }
    }

    const int vi = __brev(lane) >> 27;   // bitrev5
    const int k = vi >> 3;
    const int j = vi & 7;
    const float bias = half ? g_c[j] : 0.f;   // fold c into object half
    g_U[(obase + k) * 16 + half * 8 + j] = v[0] + bias;
}

// ---------------------------------------------------------------------------
// out[p][r] = U[s_p][r] + U[o_p][8+r]   (c already folded into U's obj half)
// PDL: pairs load issues during u_kernel's drain (independent data), then
// sync before reading g_U. 1 pair per thread, grid 256 x 256.
// ---------------------------------------------------------------------------
__global__ void __launch_bounds__(256) gather_kernel(const int* __restrict__ pairs,
                                                     float* __restrict__ out) {
    const int p = blockIdx.x * 256 + threadIdx.x;    // 0..65535
    int2 pr = __ldg(&((const int2*)pairs)[p]);       // independent of u_kernel

    cudaGridDependencySynchronize();                 // now g_U is valid

    const float4* __restrict__ U4 = (const float4*)g_U;
    float4 a0 = __ldg(&U4[pr.x * 4 + 0]);
    float4 a1 = __ldg(&U4[pr.x * 4 + 1]);
    float4 b0 = __ldg(&U4[pr.y * 4 + 2]);
    float4 b1 = __ldg(&U4[pr.y * 4 + 3]);
    float4 r0, r1;
    r0.x = a0.x + b0.x;  r0.y = a0.y + b0.y;
    r0.z = a0.z + b0.z;  r0.w = a0.w + b0.w;
    r1.x = a1.x + b1.x;  r1.y = a1.y + b1.y;
    r1.z = a1.z + b1.z;  r1.w = a1.w + b1.w;
    float4* __restrict__ O4 = (float4*)out;
    O4[p * 2 + 0] = r0;
    O4[p * 2 + 1] = r1;
}

extern "C" void kernel_launch(void* const* d_in, const int* in_sizes, int n_in,
                              void* d_out, int out_size) {
    const float* feats = (const float*)d_in[0];   // (4096, 1024) f32
    const int*   pairs = (const int*)d_in[1];     // (65536, 2) i32
    const float* W1    = (const float*)d_in[2];   // (1024, 2048) f32
    const float* b1    = (const float*)d_in[3];   // (1024,) f32
    const float* W2    = (const float*)d_in[4];   // (8, 1024) f32
    const float* b2    = (const float*)d_in[5];   // (8,) f32
    float*       out   = (float*)d_out;           // (65536, 8) f32

    m_kernel<<<128, 256>>>(W1, W2, b1, b2);

    // PDL launches: allow each kernel to launch while its predecessor drains;
    // cudaGridDependencySynchronize() inside guards the data dependency.
    cudaLaunchAttribute attr[1];
    attr[0].id = cudaLaunchAttributeProgrammaticStreamSerialization;
    attr[0].val.programmaticStreamSerializationAllowed = 1;

    {
        cudaLaunchConfig_t cfg = {};
        cfg.gridDim  = dim3(256, 1, 1);
        cfg.blockDim = dim3(256, 1, 1);
        cfg.attrs    = attr;
        cfg.numAttrs = 1;
        cfg.stream   = 0;
        cudaLaunchKernelEx(&cfg, u_kernel, feats);
    }
    {
        cudaLaunchConfig_t cfg = {};
        cfg.gridDim  = dim3(256, 1, 1);
        cfg.blockDim = dim3(256, 1, 1);
        cfg.attrs    = attr;
        cfg.numAttrs = 1;
        cfg.stream   = 0;
        cudaLaunchKernelEx(&cfg, gather_kernel, pairs, (float*)d_out);
    }
}